// round 1
// baseline (speedup 1.0000x reference)
#include <cuda_runtime.h>
#include <math.h>

#define BATCH 128
#define SEQ   50
#define DIM   512
#define HID   2048
#define VOCAB 32000
#define ROWS  (BATCH*SEQ)   // 6400
#define LN_EPS 1e-5f

// ---------------- scratch (device globals; no allocation) ----------------
__device__ float g_x0[ROWS*DIM];    // embed output / residual 0
__device__ float g_Q [ROWS*DIM];
__device__ float g_K [ROWS*DIM];
__device__ float g_V [ROWS*DIM];
__device__ float g_att[ROWS*DIM];
__device__ float g_x1[ROWS*DIM];    // after LN1
__device__ float g_h [ROWS*HID];    // FFN hidden
__device__ float g_f [ROWS*DIM];    // FFN out
__device__ float g_x2[ROWS*DIM];    // after LN2

// ---------------- embed: x = emb[idx] + pos ----------------
__global__ void embed_kernel(const int* __restrict__ idx,
                             const float* __restrict__ emb,
                             const float* __restrict__ pos,
                             float* __restrict__ x)
{
    int row = blockIdx.x;            // b*SEQ + s
    int s   = row % SEQ;
    int tok = idx[row];
    const float4* e = (const float4*)(emb + (size_t)tok * DIM);
    const float4* p = (const float4*)(pos + (size_t)s   * DIM);
    float4*       o = (float4*)(x + (size_t)row * DIM);
    for (int i = threadIdx.x; i < DIM/4; i += blockDim.x) {
        float4 a = e[i], b = p[i];
        o[i] = make_float4(a.x+b.x, a.y+b.y, a.z+b.z, a.w+b.w);
    }
}

// ---------------- generic SGEMM: C = act(A[M,K] @ W[K,N] + bias) ----------------
// BM=BN=128, BK=16, 256 threads, 8x8 register tile. M%128==0, N%128==0, K%16==0.
// ACT: 0 none, 1 sigmoid, 2 exact gelu
template<int ACT>
__global__ __launch_bounds__(256) void sgemm_kernel(
    const float* __restrict__ A, const float* __restrict__ W,
    const float* __restrict__ bias, float* __restrict__ C,
    int M, int N, int K)
{
    __shared__ float As[16][128];
    __shared__ float Ws[16][128];

    int tid = threadIdx.x;
    int tx = tid & 15, ty = tid >> 4;
    int bm = blockIdx.y * 128, bn = blockIdx.x * 128;

    float acc[8][8];
    #pragma unroll
    for (int i = 0; i < 8; i++)
        #pragma unroll
        for (int j = 0; j < 8; j++) acc[i][j] = 0.f;

    for (int kt = 0; kt < K; kt += 16) {
        #pragma unroll
        for (int r = 0; r < 2; r++) {
            int q = tid + r * 256;
            // A tile: 128 rows x 16 k  (float4 along k)
            int m   = q >> 2;
            int kk4 = (q & 3) * 4;
            float4 a = *(const float4*)(A + (size_t)(bm + m) * K + kt + kk4);
            As[kk4+0][m] = a.x; As[kk4+1][m] = a.y;
            As[kk4+2][m] = a.z; As[kk4+3][m] = a.w;
            // W tile: 16 k x 128 n (float4 along n)
            int kk = q >> 5;
            int n4 = (q & 31) * 4;
            *(float4*)(&Ws[kk][n4]) =
                *(const float4*)(W + (size_t)(kt + kk) * N + bn + n4);
        }
        __syncthreads();

        #pragma unroll
        for (int kk = 0; kk < 16; kk++) {
            float af[8], bf[8];
            #pragma unroll
            for (int i = 0; i < 8; i++) af[i] = As[kk][ty*8 + i];
            #pragma unroll
            for (int j = 0; j < 8; j++) bf[j] = Ws[kk][tx*8 + j];
            #pragma unroll
            for (int i = 0; i < 8; i++)
                #pragma unroll
                for (int j = 0; j < 8; j++)
                    acc[i][j] += af[i] * bf[j];
        }
        __syncthreads();
    }

    #pragma unroll
    for (int i = 0; i < 8; i++) {
        int m = bm + ty*8 + i;
        #pragma unroll
        for (int j = 0; j < 8; j++) {
            int n = bn + tx*8 + j;
            float v = acc[i][j] + bias[n];
            if (ACT == 1) v = 1.0f / (1.0f + expf(-v));
            else if (ACT == 2) v = 0.5f * v * (1.0f + erff(v * 0.70710678118654752f));
            C[(size_t)m * N + n] = v;
        }
    }
}

// ---------------- attention ----------------
// block per (b,i), 128 threads = 4 warps.
// logits[j] = (j<=i) ? 10 * mean_d min(1 - Q[i,d] + K[j,d], 1) : 0
// softmax over ALL 50 j (masked entries have logit exactly 0, matching jnp.where->softmax).
__global__ __launch_bounds__(128) void attn_kernel(
    const float* __restrict__ Q, const float* __restrict__ K,
    const float* __restrict__ V, float* __restrict__ O)
{
    int row = blockIdx.x;
    int b = row / SEQ, i = row % SEQ;
    int tid = threadIdx.x, warp = tid >> 5, lane = tid & 31;

    __shared__ float sQ[DIM];
    __shared__ float sp[SEQ];

    const float* q = Q + (size_t)row * DIM;
    for (int d = tid; d < DIM; d += 128) sQ[d] = q[d];
    __syncthreads();

    for (int j = warp; j < SEQ; j += 4) {
        float s = 0.f;
        if (j <= i) {
            const float* kp = K + ((size_t)b * SEQ + j) * DIM;
            for (int d = lane; d < DIM; d += 32)
                s += fminf(1.0f - sQ[d] + kp[d], 1.0f);
            #pragma unroll
            for (int o = 16; o; o >>= 1) s += __shfl_xor_sync(0xffffffffu, s, o);
            s *= (10.0f / (float)DIM);
        }
        if (lane == 0) sp[j] = s;
    }
    __syncthreads();

    if (warp == 0) {
        float m = -1e30f;
        for (int j = lane; j < SEQ; j += 32) m = fmaxf(m, sp[j]);
        #pragma unroll
        for (int o = 16; o; o >>= 1) m = fmaxf(m, __shfl_xor_sync(0xffffffffu, m, o));
        float sum = 0.f;
        float e0 = 0.f, e1 = 0.f;
        if (lane      < SEQ) { e0 = expf(sp[lane]      - m); sum += e0; }
        if (lane + 32 < SEQ) { e1 = expf(sp[lane + 32] - m); sum += e1; }
        #pragma unroll
        for (int o = 16; o; o >>= 1) sum += __shfl_xor_sync(0xffffffffu, sum, o);
        float inv = 1.0f / sum;
        if (lane      < SEQ) sp[lane]      = e0 * inv;
        if (lane + 32 < SEQ) sp[lane + 32] = e1 * inv;
    }
    __syncthreads();

    float acc[4] = {0.f, 0.f, 0.f, 0.f};
    for (int j = 0; j < SEQ; j++) {
        float p = sp[j];
        const float* v = V + ((size_t)b * SEQ + j) * DIM;
        #pragma unroll
        for (int u = 0; u < 4; u++) acc[u] += p * v[tid + u*128];
    }
    float* o = O + (size_t)row * DIM;
    #pragma unroll
    for (int u = 0; u < 4; u++) o[tid + u*128] = acc[u];
}

// ---------------- fused residual add + LayerNorm ----------------
__global__ __launch_bounds__(128) void add_ln_kernel(
    const float* __restrict__ a, const float* __restrict__ r,
    const float* __restrict__ g, const float* __restrict__ be,
    float* __restrict__ out)
{
    int row = blockIdx.x, tid = threadIdx.x;
    const float* pa = a + (size_t)row * DIM;
    const float* pr = r + (size_t)row * DIM;

    float v[4];
    float sum = 0.f;
    #pragma unroll
    for (int u = 0; u < 4; u++) {
        int d = tid + u*128;
        v[u] = pa[d] + pr[d];
        sum += v[u];
    }
    __shared__ float red[4];
    #pragma unroll
    for (int o = 16; o; o >>= 1) sum += __shfl_xor_sync(0xffffffffu, sum, o);
    if ((tid & 31) == 0) red[tid >> 5] = sum;
    __syncthreads();
    float mean = (red[0] + red[1] + red[2] + red[3]) * (1.0f / DIM);

    float vs = 0.f;
    #pragma unroll
    for (int u = 0; u < 4; u++) { float d = v[u] - mean; vs += d * d; }
    #pragma unroll
    for (int o = 16; o; o >>= 1) vs += __shfl_xor_sync(0xffffffffu, vs, o);
    __shared__ float red2[4];
    if ((tid & 31) == 0) red2[tid >> 5] = vs;
    __syncthreads();
    float var = (red2[0] + red2[1] + red2[2] + red2[3]) * (1.0f / DIM);
    float inv = rsqrtf(var + LN_EPS);

    float* po = out + (size_t)row * DIM;
    #pragma unroll
    for (int u = 0; u < 4; u++) {
        int d = tid + u*128;
        po[d] = (v[u] - mean) * inv * g[d] + be[d];
    }
}

// ---------------- launch ----------------
extern "C" void kernel_launch(void* const* d_in, const int* in_sizes, int n_in,
                              void* d_out, int out_size)
{
    const int*   idx = (const int*)  d_in[0];
    const float* emb = (const float*)d_in[1];
    const float* pos = (const float*)d_in[2];
    const float* wq  = (const float*)d_in[3];
    const float* bq  = (const float*)d_in[4];
    const float* wk  = (const float*)d_in[5];
    const float* bk  = (const float*)d_in[6];
    const float* wv  = (const float*)d_in[7];
    const float* bv  = (const float*)d_in[8];
    const float* w1  = (const float*)d_in[9];
    const float* b1  = (const float*)d_in[10];
    const float* w2  = (const float*)d_in[11];
    const float* b2  = (const float*)d_in[12];
    const float* g1  = (const float*)d_in[13];
    const float* be1 = (const float*)d_in[14];
    const float* g2  = (const float*)d_in[15];
    const float* be2 = (const float*)d_in[16];
    const float* wo  = (const float*)d_in[17];
    const float* bo  = (const float*)d_in[18];
    float* out = (float*)d_out;

    float *x0, *Qb, *Kb, *Vb, *att, *x1, *h, *f, *x2;
    cudaGetSymbolAddress((void**)&x0,  g_x0);
    cudaGetSymbolAddress((void**)&Qb,  g_Q);
    cudaGetSymbolAddress((void**)&Kb,  g_K);
    cudaGetSymbolAddress((void**)&Vb,  g_V);
    cudaGetSymbolAddress((void**)&att, g_att);
    cudaGetSymbolAddress((void**)&x1,  g_x1);
    cudaGetSymbolAddress((void**)&h,   g_h);
    cudaGetSymbolAddress((void**)&f,   g_f);
    cudaGetSymbolAddress((void**)&x2,  g_x2);

    // 1. embed
    embed_kernel<<<ROWS, 128>>>(idx, emb, pos, x0);

    // 2. Q,K,V projections
    dim3 blk(256);
    dim3 g_d(DIM/128, ROWS/128);       // (4, 50)
    sgemm_kernel<1><<<g_d, blk>>>(x0, wq, bq, Qb, ROWS, DIM, DIM);
    sgemm_kernel<1><<<g_d, blk>>>(x0, wk, bk, Kb, ROWS, DIM, DIM);
    sgemm_kernel<0><<<g_d, blk>>>(x0, wv, bv, Vb, ROWS, DIM, DIM);

    // 3. Lukasiewicz attention
    attn_kernel<<<ROWS, 128>>>(Qb, Kb, Vb, att);

    // 4. LN1(x0 + att)
    add_ln_kernel<<<ROWS, 128>>>(x0, att, g1, be1, x1);

    // 5. FFN
    dim3 g_h1(HID/128, ROWS/128);      // (16, 50)
    sgemm_kernel<2><<<g_h1, blk>>>(x1, w1, b1, h, ROWS, HID, DIM);
    sgemm_kernel<0><<<g_d,  blk>>>(h,  w2, b2, f, ROWS, DIM, HID);

    // 6. LN2(x1 + f)
    add_ln_kernel<<<ROWS, 128>>>(x1, f, g2, be2, x2);

    // 7. output projection -> d_out
    dim3 g_o(VOCAB/128, ROWS/128);     // (250, 50)
    sgemm_kernel<0><<<g_o, blk>>>(x2, wo, bo, out, ROWS, VOCAB, DIM);
}

// round 6
// speedup vs baseline: 4.1816x; 4.1816x over previous
#include <cuda_runtime.h>
#include <math.h>
#include <stdint.h>

#define BATCH 128
#define SEQ   50
#define DIM   512
#define HID   2048
#define VOCAB 32000
#define ROWS  (BATCH*SEQ)   // 6400
#define LN_EPS 1e-5f

// ---------------- scratch (device globals; no allocation) ----------------
__device__ float g_x0[ROWS*DIM];
__device__ float g_Q [ROWS*DIM];
__device__ float g_K [ROWS*DIM];
__device__ float g_V [ROWS*DIM];
__device__ float g_att[ROWS*DIM];
__device__ float g_x1[ROWS*DIM];
__device__ float g_h [ROWS*HID];
__device__ float g_f [ROWS*DIM];
__device__ float g_x2[ROWS*DIM];

// ---------------- embed: x = emb[idx] + pos ----------------
__global__ void embed_kernel(const int* __restrict__ idx,
                             const float* __restrict__ emb,
                             const float* __restrict__ pos,
                             float* __restrict__ x)
{
    int row = blockIdx.x;
    int s   = row % SEQ;
    int tok = idx[row];
    const float4* e = (const float4*)(emb + (size_t)tok * DIM);
    const float4* p = (const float4*)(pos + (size_t)s   * DIM);
    float4*       o = (float4*)(x + (size_t)row * DIM);
    for (int i = threadIdx.x; i < DIM/4; i += blockDim.x) {
        float4 a = e[i], b = p[i];
        o[i] = make_float4(a.x+b.x, a.y+b.y, a.z+b.z, a.w+b.w);
    }
}

// ---------------- generic fp32 SGEMM (used for QKV; precision reserve) --------
// BM=BN=128, BK=16, 256 threads, 8x8 register tile. ACT: 0 none, 1 sigmoid
template<int ACT>
__global__ __launch_bounds__(256) void sgemm_kernel(
    const float* __restrict__ A, const float* __restrict__ W,
    const float* __restrict__ bias, float* __restrict__ C,
    int M, int N, int K)
{
    __shared__ float As[16][128];
    __shared__ float Ws[16][128];

    int tid = threadIdx.x;
    int tx = tid & 15, ty = tid >> 4;
    int bm = blockIdx.y * 128, bn = blockIdx.x * 128;

    float acc[8][8];
    #pragma unroll
    for (int i = 0; i < 8; i++)
        #pragma unroll
        for (int j = 0; j < 8; j++) acc[i][j] = 0.f;

    for (int kt = 0; kt < K; kt += 16) {
        #pragma unroll
        for (int r = 0; r < 2; r++) {
            int q = tid + r * 256;
            int m   = q >> 2;
            int kk4 = (q & 3) * 4;
            float4 a = *(const float4*)(A + (size_t)(bm + m) * K + kt + kk4);
            As[kk4+0][m] = a.x; As[kk4+1][m] = a.y;
            As[kk4+2][m] = a.z; As[kk4+3][m] = a.w;
            int kk = q >> 5;
            int n4 = (q & 31) * 4;
            *(float4*)(&Ws[kk][n4]) =
                *(const float4*)(W + (size_t)(kt + kk) * N + bn + n4);
        }
        __syncthreads();

        #pragma unroll
        for (int kk = 0; kk < 16; kk++) {
            float af[8], bf[8];
            #pragma unroll
            for (int i = 0; i < 8; i++) af[i] = As[kk][ty*8 + i];
            #pragma unroll
            for (int j = 0; j < 8; j++) bf[j] = Ws[kk][tx*8 + j];
            #pragma unroll
            for (int i = 0; i < 8; i++)
                #pragma unroll
                for (int j = 0; j < 8; j++)
                    acc[i][j] += af[i] * bf[j];
        }
        __syncthreads();
    }

    #pragma unroll
    for (int i = 0; i < 8; i++) {
        int m = bm + ty*8 + i;
        #pragma unroll
        for (int j = 0; j < 8; j++) {
            int n = bn + tx*8 + j;
            float v = acc[i][j] + bias[n];
            if (ACT == 1) v = 1.0f / (1.0f + expf(-v));
            C[(size_t)m * N + n] = v;
        }
    }
}

// ---------------- tf32 tensor-core GEMM: C = act(A[M,K] @ W[K,N] + bias) ------
// BM=BN=128, BK=32, 256 threads = 8 warps (2 M x 4 N), warp tile 64x32.
// ACT: 0 none, 2 exact gelu
__device__ __forceinline__ uint32_t f2tf32(float f) {
    uint32_t o;
    asm("cvt.rna.tf32.f32 %0, %1;" : "=r"(o) : "f"(f));
    return o;
}

template<int ACT>
__global__ __launch_bounds__(256) void gemm_tf32_kernel(
    const float* __restrict__ A, const float* __restrict__ W,
    const float* __restrict__ bias, float* __restrict__ C,
    int M, int N, int K)
{
    __shared__ uint32_t As[128][36];   // [m][k], pad 36 -> conflict-free frags
    __shared__ uint32_t Ws[128][36];   // [n][k]  (W transposed)

    int tid  = threadIdx.x;
    int warp = tid >> 5, lane = tid & 31;
    int wm = warp >> 2, wn = warp & 3;
    int gid = lane >> 2, tig = lane & 3;
    int bm = blockIdx.y * 128, bn = blockIdx.x * 128;

    float acc[4][4][4];
    #pragma unroll
    for (int i = 0; i < 4; i++)
        #pragma unroll
        for (int j = 0; j < 4; j++)
            #pragma unroll
            for (int c = 0; c < 4; c++) acc[i][j][c] = 0.f;

    for (int kt = 0; kt < K; kt += 32) {
        // A tile: 128 m x 32 k = 1024 float4 -> 4 iters x 256 threads  (R5 bugfix)
        #pragma unroll
        for (int r = 0; r < 4; r++) {
            int q  = tid + r * 256;
            int m  = q >> 3;                   // 0..127
            int k4 = (q & 7) * 4;              // 0,4,...,28
            float4 v = *(const float4*)(A + (size_t)(bm + m) * K + kt + k4);
            *(uint4*)(&As[m][k4]) =
                make_uint4(f2tf32(v.x), f2tf32(v.y), f2tf32(v.z), f2tf32(v.w));
        }
        // W tile transposed: lanes span contiguous n (coalesced), 8 k per thread.
        #pragma unroll
        for (int r = 0; r < 2; r++) {
            int q  = tid + r * 256;            // 0..511
            int n  = q & 127;
            int k4 = (q >> 7) * 8;             // 0,8,16,24
            uint32_t u0 = f2tf32(W[(size_t)(kt + k4 + 0) * N + bn + n]);
            uint32_t u1 = f2tf32(W[(size_t)(kt + k4 + 1) * N + bn + n]);
            uint32_t u2 = f2tf32(W[(size_t)(kt + k4 + 2) * N + bn + n]);
            uint32_t u3 = f2tf32(W[(size_t)(kt + k4 + 3) * N + bn + n]);
            uint32_t u4 = f2tf32(W[(size_t)(kt + k4 + 4) * N + bn + n]);
            uint32_t u5 = f2tf32(W[(size_t)(kt + k4 + 5) * N + bn + n]);
            uint32_t u6 = f2tf32(W[(size_t)(kt + k4 + 6) * N + bn + n]);
            uint32_t u7 = f2tf32(W[(size_t)(kt + k4 + 7) * N + bn + n]);
            *(uint4*)(&Ws[n][k4])     = make_uint4(u0, u1, u2, u3);
            *(uint4*)(&Ws[n][k4 + 4]) = make_uint4(u4, u5, u6, u7);
        }
        __syncthreads();

        #pragma unroll
        for (int kk = 0; kk < 32; kk += 8) {
            uint32_t af[4][4], bf[4][2];
            #pragma unroll
            for (int mt = 0; mt < 4; mt++) {
                int m = wm * 64 + mt * 16;
                af[mt][0] = As[m + gid    ][kk + tig    ];
                af[mt][1] = As[m + gid + 8][kk + tig    ];
                af[mt][2] = As[m + gid    ][kk + tig + 4];
                af[mt][3] = As[m + gid + 8][kk + tig + 4];
            }
            #pragma unroll
            for (int nt = 0; nt < 4; nt++) {
                int n = wn * 32 + nt * 8;
                bf[nt][0] = Ws[n + gid][kk + tig    ];
                bf[nt][1] = Ws[n + gid][kk + tig + 4];
            }
            #pragma unroll
            for (int mt = 0; mt < 4; mt++)
                #pragma unroll
                for (int nt = 0; nt < 4; nt++) {
                    asm volatile(
                        "mma.sync.aligned.m16n8k8.row.col.f32.tf32.tf32.f32 "
                        "{%0,%1,%2,%3}, {%4,%5,%6,%7}, {%8,%9}, {%0,%1,%2,%3};"
                        : "+f"(acc[mt][nt][0]), "+f"(acc[mt][nt][1]),
                          "+f"(acc[mt][nt][2]), "+f"(acc[mt][nt][3])
                        : "r"(af[mt][0]), "r"(af[mt][1]), "r"(af[mt][2]), "r"(af[mt][3]),
                          "r"(bf[nt][0]), "r"(bf[nt][1]));
                }
        }
        __syncthreads();
    }

    #pragma unroll
    for (int mt = 0; mt < 4; mt++) {
        int m = bm + wm * 64 + mt * 16 + gid;
        #pragma unroll
        for (int nt = 0; nt < 4; nt++) {
            int n = bn + wn * 32 + nt * 8 + 2 * tig;
            float b0 = bias[n], b1 = bias[n + 1];
            float v00 = acc[mt][nt][0] + b0, v01 = acc[mt][nt][1] + b1;
            float v10 = acc[mt][nt][2] + b0, v11 = acc[mt][nt][3] + b1;
            if (ACT == 2) {
                v00 = 0.5f * v00 * (1.0f + erff(v00 * 0.70710678118654752f));
                v01 = 0.5f * v01 * (1.0f + erff(v01 * 0.70710678118654752f));
                v10 = 0.5f * v10 * (1.0f + erff(v10 * 0.70710678118654752f));
                v11 = 0.5f * v11 * (1.0f + erff(v11 * 0.70710678118654752f));
            }
            *(float2*)(C + (size_t)m       * N + n) = make_float2(v00, v01);
            *(float2*)(C + (size_t)(m + 8) * N + n) = make_float2(v10, v11);
        }
    }
}

// ---------------- attention ----------------
__global__ __launch_bounds__(128) void attn_kernel(
    const float* __restrict__ Q, const float* __restrict__ K,
    const float* __restrict__ V, float* __restrict__ O)
{
    int row = blockIdx.x;
    int b = row / SEQ, i = row % SEQ;
    int tid = threadIdx.x, warp = tid >> 5, lane = tid & 31;

    __shared__ float sQ[DIM];
    __shared__ float sp[SEQ];

    const float* q = Q + (size_t)row * DIM;
    for (int d = tid; d < DIM; d += 128) sQ[d] = q[d];
    __syncthreads();

    for (int j = warp; j < SEQ; j += 4) {
        float s = 0.f;
        if (j <= i) {
            const float* kp = K + ((size_t)b * SEQ + j) * DIM;
            for (int d = lane; d < DIM; d += 32)
                s += fminf(1.0f - sQ[d] + kp[d], 1.0f);
            #pragma unroll
            for (int o = 16; o; o >>= 1) s += __shfl_xor_sync(0xffffffffu, s, o);
            s *= (10.0f / (float)DIM);
        }
        if (lane == 0) sp[j] = s;
    }
    __syncthreads();

    if (warp == 0) {
        float m = -1e30f;
        for (int j = lane; j < SEQ; j += 32) m = fmaxf(m, sp[j]);
        #pragma unroll
        for (int o = 16; o; o >>= 1) m = fmaxf(m, __shfl_xor_sync(0xffffffffu, m, o));
        float sum = 0.f;
        float e0 = 0.f, e1 = 0.f;
        if (lane      < SEQ) { e0 = expf(sp[lane]      - m); sum += e0; }
        if (lane + 32 < SEQ) { e1 = expf(sp[lane + 32] - m); sum += e1; }
        #pragma unroll
        for (int o = 16; o; o >>= 1) sum += __shfl_xor_sync(0xffffffffu, sum, o);
        float inv = 1.0f / sum;
        if (lane      < SEQ) sp[lane]      = e0 * inv;
        if (lane + 32 < SEQ) sp[lane + 32] = e1 * inv;
    }
    __syncthreads();

    float acc[4] = {0.f, 0.f, 0.f, 0.f};
    for (int j = 0; j < SEQ; j++) {
        float p = sp[j];
        const float* v = V + ((size_t)b * SEQ + j) * DIM;
        #pragma unroll
        for (int u = 0; u < 4; u++) acc[u] += p * v[tid + u*128];
    }
    float* o = O + (size_t)row * DIM;
    #pragma unroll
    for (int u = 0; u < 4; u++) o[tid + u*128] = acc[u];
}

// ---------------- fused residual add + LayerNorm ----------------
__global__ __launch_bounds__(128) void add_ln_kernel(
    const float* __restrict__ a, const float* __restrict__ r,
    const float* __restrict__ g, const float* __restrict__ be,
    float* __restrict__ out)
{
    int row = blockIdx.x, tid = threadIdx.x;
    const float* pa = a + (size_t)row * DIM;
    const float* pr = r + (size_t)row * DIM;

    float v[4];
    float sum = 0.f;
    #pragma unroll
    for (int u = 0; u < 4; u++) {
        int d = tid + u*128;
        v[u] = pa[d] + pr[d];
        sum += v[u];
    }
    __shared__ float red[4];
    #pragma unroll
    for (int o = 16; o; o >>= 1) sum += __shfl_xor_sync(0xffffffffu, sum, o);
    if ((tid & 31) == 0) red[tid >> 5] = sum;
    __syncthreads();
    float mean = (red[0] + red[1] + red[2] + red[3]) * (1.0f / DIM);

    float vs = 0.f;
    #pragma unroll
    for (int u = 0; u < 4; u++) { float d = v[u] - mean; vs += d * d; }
    #pragma unroll
    for (int o = 16; o; o >>= 1) vs += __shfl_xor_sync(0xffffffffu, vs, o);
    __shared__ float red2[4];
    if ((tid & 31) == 0) red2[tid >> 5] = vs;
    __syncthreads();
    float var = (red2[0] + red2[1] + red2[2] + red2[3]) * (1.0f / DIM);
    float inv = rsqrtf(var + LN_EPS);

    float* po = out + (size_t)row * DIM;
    #pragma unroll
    for (int u = 0; u < 4; u++) {
        int d = tid + u*128;
        po[d] = (v[u] - mean) * inv * g[d] + be[d];
    }
}

// ---------------- launch ----------------
extern "C" void kernel_launch(void* const* d_in, const int* in_sizes, int n_in,
                              void* d_out, int out_size)
{
    const int*   idx = (const int*)  d_in[0];
    const float* emb = (const float*)d_in[1];
    const float* pos = (const float*)d_in[2];
    const float* wq  = (const float*)d_in[3];
    const float* bq  = (const float*)d_in[4];
    const float* wk  = (const float*)d_in[5];
    const float* bk  = (const float*)d_in[6];
    const float* wv  = (const float*)d_in[7];
    const float* bv  = (const float*)d_in[8];
    const float* w1  = (const float*)d_in[9];
    const float* b1  = (const float*)d_in[10];
    const float* w2  = (const float*)d_in[11];
    const float* b2  = (const float*)d_in[12];
    const float* g1  = (const float*)d_in[13];
    const float* be1 = (const float*)d_in[14];
    const float* g2  = (const float*)d_in[15];
    const float* be2 = (const float*)d_in[16];
    const float* wo  = (const float*)d_in[17];
    const float* bo  = (const float*)d_in[18];
    float* out = (float*)d_out;

    float *x0, *Qb, *Kb, *Vb, *att, *x1, *h, *f, *x2;
    cudaGetSymbolAddress((void**)&x0,  g_x0);
    cudaGetSymbolAddress((void**)&Qb,  g_Q);
    cudaGetSymbolAddress((void**)&Kb,  g_K);
    cudaGetSymbolAddress((void**)&Vb,  g_V);
    cudaGetSymbolAddress((void**)&att, g_att);
    cudaGetSymbolAddress((void**)&x1,  g_x1);
    cudaGetSymbolAddress((void**)&h,   g_h);
    cudaGetSymbolAddress((void**)&f,   g_f);
    cudaGetSymbolAddress((void**)&x2,  g_x2);

    // 1. embed
    embed_kernel<<<ROWS, 128>>>(idx, emb, pos, x0);

    // 2. Q,K,V projections (exact fp32 — attention path amplifies error)
    dim3 blk(256);
    dim3 g_d(DIM/128, ROWS/128);       // (4, 50)
    sgemm_kernel<1><<<g_d, blk>>>(x0, wq, bq, Qb, ROWS, DIM, DIM);
    sgemm_kernel<1><<<g_d, blk>>>(x0, wk, bk, Kb, ROWS, DIM, DIM);
    sgemm_kernel<0><<<g_d, blk>>>(x0, wv, bv, Vb, ROWS, DIM, DIM);

    // 3. Lukasiewicz attention
    attn_kernel<<<ROWS, 128>>>(Qb, Kb, Vb, att);

    // 4. LN1(x0 + att)
    add_ln_kernel<<<ROWS, 128>>>(x0, att, g1, be1, x1);

    // 5. FFN (tf32 tensor cores, gelu fused in first GEMM)
    dim3 g_h1(HID/128, ROWS/128);      // (16, 50)
    gemm_tf32_kernel<2><<<g_h1, blk>>>(x1, w1, b1, h, ROWS, HID, DIM);
    gemm_tf32_kernel<0><<<g_d,  blk>>>(h,  w2, b2, f, ROWS, DIM, HID);

    // 6. LN2(x1 + f)
    add_ln_kernel<<<ROWS, 128>>>(x1, f, g2, be2, x2);

    // 7. output projection -> d_out (tf32 tensor cores)
    dim3 g_o(VOCAB/128, ROWS/128);     // (250, 50)
    gemm_tf32_kernel<0><<<g_o, blk>>>(x2, wo, bo, out, ROWS, VOCAB, DIM);
}

// round 7
// speedup vs baseline: 4.6637x; 1.1153x over previous
#include <cuda_runtime.h>
#include <math.h>
#include <stdint.h>

#define BATCH 128
#define SEQ   50
#define DIM   512
#define HID   2048
#define VOCAB 32000
#define ROWS  (BATCH*SEQ)   // 6400
#define LN_EPS 1e-5f

// ---------------- scratch (device globals; no allocation) ----------------
__device__ float g_x0[ROWS*DIM];
__device__ float g_Q [ROWS*DIM];
__device__ float g_K [ROWS*DIM];
__device__ float g_V [ROWS*DIM];
__device__ float g_att[ROWS*DIM];
__device__ float g_x1[ROWS*DIM];
__device__ float g_h [ROWS*HID];
__device__ float g_f [ROWS*DIM];
__device__ float g_x2[ROWS*DIM];

// ---------------- embed: x = emb[idx] + pos ----------------
__global__ void embed_kernel(const int* __restrict__ idx,
                             const float* __restrict__ emb,
                             const float* __restrict__ pos,
                             float* __restrict__ x)
{
    int row = blockIdx.x;
    int s   = row % SEQ;
    int tok = idx[row];
    const float4* e = (const float4*)(emb + (size_t)tok * DIM);
    const float4* p = (const float4*)(pos + (size_t)s   * DIM);
    float4*       o = (float4*)(x + (size_t)row * DIM);
    for (int i = threadIdx.x; i < DIM/4; i += blockDim.x) {
        float4 a = e[i], b = p[i];
        o[i] = make_float4(a.x+b.x, a.y+b.y, a.z+b.z, a.w+b.w);
    }
}

// ---------------- tf32 tensor-core GEMM, 2-stage cp.async pipeline ------------
// C = act(A[M,K] @ W[K,N] + bias).  BM=BN=128, BK=32, 256 threads = 8 warps
// (2 M x 4 N), warp tile 64x32.  ACT: 0 none, 1 sigmoid, 2 exact gelu.
//
// smem per stage: A [128][36] fp32 (row stride 144B, 16B-mult; frag bank
// 4*gid+tig bijective), B [32][136] fp32 (row stride 544B; frag bank 8*tig+gid
// bijective).  Raw fp32 via cp.async.cg; cvt->tf32 after fragment LDS.
#define STG_F (128*36 + 32*136)      // 8960 floats per stage
#define SMEM_BYTES (2 * STG_F * 4)   // 71680

__device__ __forceinline__ void cp_async16(uint32_t dst, const void* src) {
    asm volatile("cp.async.cg.shared.global [%0], [%1], 16;\n" :: "r"(dst), "l"(src));
}
__device__ __forceinline__ uint32_t f2tf32(float f) {
    uint32_t o;
    asm("cvt.rna.tf32.f32 %0, %1;" : "=r"(o) : "f"(f));
    return o;
}

template<int ACT>
__global__ __launch_bounds__(256) void gemm_tf32_pipe(
    const float* __restrict__ A, const float* __restrict__ W,
    const float* __restrict__ bias, float* __restrict__ C,
    int M, int N, int K)
{
    extern __shared__ float sm[];

    int tid  = threadIdx.x;
    int warp = tid >> 5, lane = tid & 31;
    int wm = warp >> 2, wn = warp & 3;
    int gid = lane >> 2, tig = lane & 3;
    int bm = blockIdx.y * 128, bn = blockIdx.x * 128;

    uint32_t smem_u32;
    asm("{ .reg .u64 t; cvta.to.shared.u64 t, %1; cvt.u32.u64 %0, t; }"
        : "=r"(smem_u32) : "l"(sm));

    float acc[4][4][4];
    #pragma unroll
    for (int i = 0; i < 4; i++)
        #pragma unroll
        for (int j = 0; j < 4; j++)
            #pragma unroll
            for (int c = 0; c < 4; c++) acc[i][j][c] = 0.f;

    const int T = K / 32;

    auto issue = [&](int t) {
        int kt = t * 32;
        uint32_t base = smem_u32 + (uint32_t)(t & 1) * (STG_F * 4);
        // A tile: 128 m x 32 k  (8 chunks/row, 4 per thread)
        #pragma unroll
        for (int r = 0; r < 4; r++) {
            int q  = tid + r * 256;
            int m  = q >> 3;
            int k4 = (q & 7) * 4;
            cp_async16(base + (uint32_t)(m * 36 + k4) * 4,
                       A + (size_t)(bm + m) * K + kt + k4);
        }
        // B tile: 32 k x 128 n  (contiguous n chunks)
        #pragma unroll
        for (int r = 0; r < 4; r++) {
            int q  = tid + r * 256;
            int k  = q >> 5;
            int n4 = (q & 31) * 4;
            cp_async16(base + (uint32_t)(128*36 + k * 136 + n4) * 4,
                       W + (size_t)(kt + k) * N + bn + n4);
        }
        asm volatile("cp.async.commit_group;\n" ::);
    };

    issue(0);

    for (int t = 0; t < T; t++) {
        if (t + 1 < T) {
            issue(t + 1);
            asm volatile("cp.async.wait_group 1;\n" ::);
        } else {
            asm volatile("cp.async.wait_group 0;\n" ::);
        }
        __syncthreads();

        const float* As_ = sm + (t & 1) * STG_F;
        const float* Bs_ = As_ + 128*36;

        #pragma unroll
        for (int kk = 0; kk < 32; kk += 8) {
            uint32_t af[4][4], bf[4][2];
            #pragma unroll
            for (int mt = 0; mt < 4; mt++) {
                int m0 = wm * 64 + mt * 16;
                af[mt][0] = f2tf32(As_[(m0 + gid    ) * 36 + kk + tig    ]);
                af[mt][1] = f2tf32(As_[(m0 + gid + 8) * 36 + kk + tig    ]);
                af[mt][2] = f2tf32(As_[(m0 + gid    ) * 36 + kk + tig + 4]);
                af[mt][3] = f2tf32(As_[(m0 + gid + 8) * 36 + kk + tig + 4]);
            }
            #pragma unroll
            for (int nt = 0; nt < 4; nt++) {
                int n0 = wn * 32 + nt * 8;
                bf[nt][0] = f2tf32(Bs_[(kk + tig    ) * 136 + n0 + gid]);
                bf[nt][1] = f2tf32(Bs_[(kk + tig + 4) * 136 + n0 + gid]);
            }
            #pragma unroll
            for (int mt = 0; mt < 4; mt++)
                #pragma unroll
                for (int nt = 0; nt < 4; nt++) {
                    asm volatile(
                        "mma.sync.aligned.m16n8k8.row.col.f32.tf32.tf32.f32 "
                        "{%0,%1,%2,%3}, {%4,%5,%6,%7}, {%8,%9}, {%0,%1,%2,%3};"
                        : "+f"(acc[mt][nt][0]), "+f"(acc[mt][nt][1]),
                          "+f"(acc[mt][nt][2]), "+f"(acc[mt][nt][3])
                        : "r"(af[mt][0]), "r"(af[mt][1]), "r"(af[mt][2]), "r"(af[mt][3]),
                          "r"(bf[nt][0]), "r"(bf[nt][1]));
                }
        }
        __syncthreads();
    }

    // epilogue: c0 -> (gid, 2*tig), c1 -> (gid, 2*tig+1), c2/c3 -> +8 rows
    #pragma unroll
    for (int mt = 0; mt < 4; mt++) {
        int m = bm + wm * 64 + mt * 16 + gid;
        #pragma unroll
        for (int nt = 0; nt < 4; nt++) {
            int n = bn + wn * 32 + nt * 8 + 2 * tig;
            float b0 = bias[n], b1 = bias[n + 1];
            float v00 = acc[mt][nt][0] + b0, v01 = acc[mt][nt][1] + b1;
            float v10 = acc[mt][nt][2] + b0, v11 = acc[mt][nt][3] + b1;
            if (ACT == 1) {
                v00 = 1.0f / (1.0f + expf(-v00));
                v01 = 1.0f / (1.0f + expf(-v01));
                v10 = 1.0f / (1.0f + expf(-v10));
                v11 = 1.0f / (1.0f + expf(-v11));
            } else if (ACT == 2) {
                v00 = 0.5f * v00 * (1.0f + erff(v00 * 0.70710678118654752f));
                v01 = 0.5f * v01 * (1.0f + erff(v01 * 0.70710678118654752f));
                v10 = 0.5f * v10 * (1.0f + erff(v10 * 0.70710678118654752f));
                v11 = 0.5f * v11 * (1.0f + erff(v11 * 0.70710678118654752f));
            }
            *(float2*)(C + (size_t)m       * N + n) = make_float2(v00, v01);
            *(float2*)(C + (size_t)(m + 8) * N + n) = make_float2(v10, v11);
        }
    }
}

// ---------------- attention ----------------
__global__ __launch_bounds__(128) void attn_kernel(
    const float* __restrict__ Q, const float* __restrict__ K,
    const float* __restrict__ V, float* __restrict__ O)
{
    int row = blockIdx.x;
    int b = row / SEQ, i = row % SEQ;
    int tid = threadIdx.x, warp = tid >> 5, lane = tid & 31;

    __shared__ float sQ[DIM];
    __shared__ float sp[SEQ];

    const float* q = Q + (size_t)row * DIM;
    for (int d = tid; d < DIM; d += 128) sQ[d] = q[d];
    __syncthreads();

    for (int j = warp; j < SEQ; j += 4) {
        float s = 0.f;
        if (j <= i) {
            const float* kp = K + ((size_t)b * SEQ + j) * DIM;
            for (int d = lane; d < DIM; d += 32)
                s += fminf(1.0f - sQ[d] + kp[d], 1.0f);
            #pragma unroll
            for (int o = 16; o; o >>= 1) s += __shfl_xor_sync(0xffffffffu, s, o);
            s *= (10.0f / (float)DIM);
        }
        if (lane == 0) sp[j] = s;
    }
    __syncthreads();

    if (warp == 0) {
        float m = -1e30f;
        for (int j = lane; j < SEQ; j += 32) m = fmaxf(m, sp[j]);
        #pragma unroll
        for (int o = 16; o; o >>= 1) m = fmaxf(m, __shfl_xor_sync(0xffffffffu, m, o));
        float sum = 0.f;
        float e0 = 0.f, e1 = 0.f;
        if (lane      < SEQ) { e0 = expf(sp[lane]      - m); sum += e0; }
        if (lane + 32 < SEQ) { e1 = expf(sp[lane + 32] - m); sum += e1; }
        #pragma unroll
        for (int o = 16; o; o >>= 1) sum += __shfl_xor_sync(0xffffffffu, sum, o);
        float inv = 1.0f / sum;
        if (lane      < SEQ) sp[lane]      = e0 * inv;
        if (lane + 32 < SEQ) sp[lane + 32] = e1 * inv;
    }
    __syncthreads();

    float acc[4] = {0.f, 0.f, 0.f, 0.f};
    for (int j = 0; j < SEQ; j++) {
        float p = sp[j];
        const float* v = V + ((size_t)b * SEQ + j) * DIM;
        #pragma unroll
        for (int u = 0; u < 4; u++) acc[u] += p * v[tid + u*128];
    }
    float* o = O + (size_t)row * DIM;
    #pragma unroll
    for (int u = 0; u < 4; u++) o[tid + u*128] = acc[u];
}

// ---------------- fused residual add + LayerNorm ----------------
__global__ __launch_bounds__(128) void add_ln_kernel(
    const float* __restrict__ a, const float* __restrict__ r,
    const float* __restrict__ g, const float* __restrict__ be,
    float* __restrict__ out)
{
    int row = blockIdx.x, tid = threadIdx.x;
    const float* pa = a + (size_t)row * DIM;
    const float* pr = r + (size_t)row * DIM;

    float v[4];
    float sum = 0.f;
    #pragma unroll
    for (int u = 0; u < 4; u++) {
        int d = tid + u*128;
        v[u] = pa[d] + pr[d];
        sum += v[u];
    }
    __shared__ float red[4];
    #pragma unroll
    for (int o = 16; o; o >>= 1) sum += __shfl_xor_sync(0xffffffffu, sum, o);
    if ((tid & 31) == 0) red[tid >> 5] = sum;
    __syncthreads();
    float mean = (red[0] + red[1] + red[2] + red[3]) * (1.0f / DIM);

    float vs = 0.f;
    #pragma unroll
    for (int u = 0; u < 4; u++) { float d = v[u] - mean; vs += d * d; }
    #pragma unroll
    for (int o = 16; o; o >>= 1) vs += __shfl_xor_sync(0xffffffffu, vs, o);
    __shared__ float red2[4];
    if ((tid & 31) == 0) red2[tid >> 5] = vs;
    __syncthreads();
    float var = (red2[0] + red2[1] + red2[2] + red2[3]) * (1.0f / DIM);
    float inv = rsqrtf(var + LN_EPS);

    float* po = out + (size_t)row * DIM;
    #pragma unroll
    for (int u = 0; u < 4; u++) {
        int d = tid + u*128;
        po[d] = (v[u] - mean) * inv * g[d] + be[d];
    }
}

// ---------------- launch ----------------
extern "C" void kernel_launch(void* const* d_in, const int* in_sizes, int n_in,
                              void* d_out, int out_size)
{
    const int*   idx = (const int*)  d_in[0];
    const float* emb = (const float*)d_in[1];
    const float* pos = (const float*)d_in[2];
    const float* wq  = (const float*)d_in[3];
    const float* bq  = (const float*)d_in[4];
    const float* wk  = (const float*)d_in[5];
    const float* bk  = (const float*)d_in[6];
    const float* wv  = (const float*)d_in[7];
    const float* bv  = (const float*)d_in[8];
    const float* w1  = (const float*)d_in[9];
    const float* b1  = (const float*)d_in[10];
    const float* w2  = (const float*)d_in[11];
    const float* b2  = (const float*)d_in[12];
    const float* g1  = (const float*)d_in[13];
    const float* be1 = (const float*)d_in[14];
    const float* g2  = (const float*)d_in[15];
    const float* be2 = (const float*)d_in[16];
    const float* wo  = (const float*)d_in[17];
    const float* bo  = (const float*)d_in[18];
    float* out = (float*)d_out;

    float *x0, *Qb, *Kb, *Vb, *att, *x1, *h, *f, *x2;
    cudaGetSymbolAddress((void**)&x0,  g_x0);
    cudaGetSymbolAddress((void**)&Qb,  g_Q);
    cudaGetSymbolAddress((void**)&Kb,  g_K);
    cudaGetSymbolAddress((void**)&Vb,  g_V);
    cudaGetSymbolAddress((void**)&att, g_att);
    cudaGetSymbolAddress((void**)&x1,  g_x1);
    cudaGetSymbolAddress((void**)&h,   g_h);
    cudaGetSymbolAddress((void**)&f,   g_f);
    cudaGetSymbolAddress((void**)&x2,  g_x2);

    // allow 70KB dynamic smem (idempotent; legal during graph capture)
    cudaFuncSetAttribute(gemm_tf32_pipe<0>, cudaFuncAttributeMaxDynamicSharedMemorySize, SMEM_BYTES);
    cudaFuncSetAttribute(gemm_tf32_pipe<1>, cudaFuncAttributeMaxDynamicSharedMemorySize, SMEM_BYTES);
    cudaFuncSetAttribute(gemm_tf32_pipe<2>, cudaFuncAttributeMaxDynamicSharedMemorySize, SMEM_BYTES);

    // 1. embed
    embed_kernel<<<ROWS, 128>>>(idx, emb, pos, x0);

    // 2. Q,K,V projections (tf32; sigmoid fused for Q,K)
    dim3 blk(256);
    dim3 g_d(DIM/128, ROWS/128);       // (4, 50)
    gemm_tf32_pipe<1><<<g_d, blk, SMEM_BYTES>>>(x0, wq, bq, Qb, ROWS, DIM, DIM);
    gemm_tf32_pipe<1><<<g_d, blk, SMEM_BYTES>>>(x0, wk, bk, Kb, ROWS, DIM, DIM);
    gemm_tf32_pipe<0><<<g_d, blk, SMEM_BYTES>>>(x0, wv, bv, Vb, ROWS, DIM, DIM);

    // 3. Lukasiewicz attention
    attn_kernel<<<ROWS, 128>>>(Qb, Kb, Vb, att);

    // 4. LN1(x0 + att)
    add_ln_kernel<<<ROWS, 128>>>(x0, att, g1, be1, x1);

    // 5. FFN (tf32, gelu fused)
    dim3 g_h1(HID/128, ROWS/128);      // (16, 50)
    gemm_tf32_pipe<2><<<g_h1, blk, SMEM_BYTES>>>(x1, w1, b1, h, ROWS, HID, DIM);
    gemm_tf32_pipe<0><<<g_d,  blk, SMEM_BYTES>>>(h,  w2, b2, f, ROWS, DIM, HID);

    // 6. LN2(x1 + f)
    add_ln_kernel<<<ROWS, 128>>>(x1, f, g2, be2, x2);

    // 7. output projection -> d_out (tf32)
    dim3 g_o(VOCAB/128, ROWS/128);     // (250, 50)
    gemm_tf32_pipe<0><<<g_o, blk, SMEM_BYTES>>>(x2, wo, bo, out, ROWS, VOCAB, DIM);
}

// round 8
// speedup vs baseline: 5.2212x; 1.1195x over previous
#include <cuda_runtime.h>
#include <math.h>
#include <stdint.h>

#define BATCH 128
#define SEQ   50
#define DIM   512
#define HID   2048
#define VOCAB 32000
#define ROWS  (BATCH*SEQ)   // 6400
#define LN_EPS 1e-5f

// ---------------- scratch (device globals; no allocation) ----------------
__device__ float g_x0[ROWS*DIM];
__device__ float g_Q [ROWS*DIM];
__device__ float g_K [ROWS*DIM];
__device__ float g_V [ROWS*DIM];
__device__ float g_att[ROWS*DIM];
__device__ float g_x1[ROWS*DIM];
__device__ float g_h [ROWS*HID];
__device__ float g_f [ROWS*DIM];
__device__ float g_x2[ROWS*DIM];

// ---------------- embed: x = emb[idx] + pos ----------------
__global__ void embed_kernel(const int* __restrict__ idx,
                             const float* __restrict__ emb,
                             const float* __restrict__ pos,
                             float* __restrict__ x)
{
    int row = blockIdx.x;
    int s   = row % SEQ;
    int tok = idx[row];
    const float4* e = (const float4*)(emb + (size_t)tok * DIM);
    const float4* p = (const float4*)(pos + (size_t)s   * DIM);
    float4*       o = (float4*)(x + (size_t)row * DIM);
    for (int i = threadIdx.x; i < DIM/4; i += blockDim.x) {
        float4 a = e[i], b = p[i];
        o[i] = make_float4(a.x+b.x, a.y+b.y, a.z+b.z, a.w+b.w);
    }
}

// ---------------- tf32 tensor-core GEMM, 2-stage cp.async pipeline ------------
// C = act(A[M,K] @ W[K,N] + bias).  BM=128, BN=256, BK=32, 256 threads =
// 8 warps (2 M x 4 N), warp tile 64x64 (MMA-bound: 21.3 FLOP/smem-byte).
// ACT: 0 none, 1 sigmoid, 2 exact gelu.
//
// smem/stage: A [128][36] fp32 (bank 4*gid+tig bijective), B [32][264] fp32
// (264%32=8 -> bank 8*tig+gid bijective). Raw fp32 via cp.async.cg; cvt->tf32
// after fragment LDS (alu pipe, overlapped).
#define STG_F (128*36 + 32*264)      // 13056 floats per stage
#define SMEM_BYTES (2 * STG_F * 4)   // 104448

__device__ __forceinline__ void cp_async16(uint32_t dst, const void* src) {
    asm volatile("cp.async.cg.shared.global [%0], [%1], 16;\n" :: "r"(dst), "l"(src));
}
__device__ __forceinline__ uint32_t f2tf32(float f) {
    uint32_t o;
    asm("cvt.rna.tf32.f32 %0, %1;" : "=r"(o) : "f"(f));
    return o;
}

template<int ACT>
__global__ __launch_bounds__(256) void gemm_tf32_pipe(
    const float* __restrict__ A, const float* __restrict__ W,
    const float* __restrict__ bias, float* __restrict__ C,
    int M, int N, int K)
{
    extern __shared__ float sm[];

    int tid  = threadIdx.x;
    int warp = tid >> 5, lane = tid & 31;
    int wm = warp >> 2, wn = warp & 3;
    int gid = lane >> 2, tig = lane & 3;
    int bm = blockIdx.y * 128, bn = blockIdx.x * 256;

    uint32_t smem_u32;
    asm("{ .reg .u64 t; cvta.to.shared.u64 t, %1; cvt.u32.u64 %0, t; }"
        : "=r"(smem_u32) : "l"(sm));

    float acc[4][8][4];
    #pragma unroll
    for (int i = 0; i < 4; i++)
        #pragma unroll
        for (int j = 0; j < 8; j++)
            #pragma unroll
            for (int c = 0; c < 4; c++) acc[i][j][c] = 0.f;

    const int T = K / 32;

    auto issue = [&](int t) {
        int kt = t * 32;
        uint32_t base = smem_u32 + (uint32_t)(t & 1) * (STG_F * 4);
        // A tile: 128 m x 32 k  (8 chunks/row; 1024 chunks -> 4/thread)
        #pragma unroll
        for (int r = 0; r < 4; r++) {
            int q  = tid + r * 256;
            int m  = q >> 3;
            int k4 = (q & 7) * 4;
            cp_async16(base + (uint32_t)(m * 36 + k4) * 4,
                       A + (size_t)(bm + m) * K + kt + k4);
        }
        // B tile: 32 k x 256 n  (64 chunks/row; 2048 chunks -> 8/thread)
        #pragma unroll
        for (int r = 0; r < 8; r++) {
            int q  = tid + r * 256;
            int k  = q >> 6;
            int n4 = (q & 63) * 4;
            cp_async16(base + (uint32_t)(128*36 + k * 264 + n4) * 4,
                       W + (size_t)(kt + k) * N + bn + n4);
        }
        asm volatile("cp.async.commit_group;\n" ::);
    };

    issue(0);

    for (int t = 0; t < T; t++) {
        if (t + 1 < T) {
            issue(t + 1);
            asm volatile("cp.async.wait_group 1;\n" ::);
        } else {
            asm volatile("cp.async.wait_group 0;\n" ::);
        }
        __syncthreads();

        const float* As_ = sm + (t & 1) * STG_F;
        const float* Bs_ = As_ + 128*36;

        #pragma unroll
        for (int kk = 0; kk < 32; kk += 8) {
            uint32_t af[4][4], bf[8][2];
            #pragma unroll
            for (int mt = 0; mt < 4; mt++) {
                int m0 = wm * 64 + mt * 16;
                af[mt][0] = f2tf32(As_[(m0 + gid    ) * 36 + kk + tig    ]);
                af[mt][1] = f2tf32(As_[(m0 + gid + 8) * 36 + kk + tig    ]);
                af[mt][2] = f2tf32(As_[(m0 + gid    ) * 36 + kk + tig + 4]);
                af[mt][3] = f2tf32(As_[(m0 + gid + 8) * 36 + kk + tig + 4]);
            }
            #pragma unroll
            for (int nt = 0; nt < 8; nt++) {
                int n0 = wn * 64 + nt * 8;
                bf[nt][0] = f2tf32(Bs_[(kk + tig    ) * 264 + n0 + gid]);
                bf[nt][1] = f2tf32(Bs_[(kk + tig + 4) * 264 + n0 + gid]);
            }
            #pragma unroll
            for (int mt = 0; mt < 4; mt++)
                #pragma unroll
                for (int nt = 0; nt < 8; nt++) {
                    asm volatile(
                        "mma.sync.aligned.m16n8k8.row.col.f32.tf32.tf32.f32 "
                        "{%0,%1,%2,%3}, {%4,%5,%6,%7}, {%8,%9}, {%0,%1,%2,%3};"
                        : "+f"(acc[mt][nt][0]), "+f"(acc[mt][nt][1]),
                          "+f"(acc[mt][nt][2]), "+f"(acc[mt][nt][3])
                        : "r"(af[mt][0]), "r"(af[mt][1]), "r"(af[mt][2]), "r"(af[mt][3]),
                          "r"(bf[nt][0]), "r"(bf[nt][1]));
                }
        }
        __syncthreads();
    }

    // epilogue: c0 -> (gid, 2*tig), c1 -> (gid, 2*tig+1), c2/c3 -> +8 rows
    #pragma unroll
    for (int mt = 0; mt < 4; mt++) {
        int m = bm + wm * 64 + mt * 16 + gid;
        #pragma unroll
        for (int nt = 0; nt < 8; nt++) {
            int n = bn + wn * 64 + nt * 8 + 2 * tig;
            float b0 = bias[n], b1 = bias[n + 1];
            float v00 = acc[mt][nt][0] + b0, v01 = acc[mt][nt][1] + b1;
            float v10 = acc[mt][nt][2] + b0, v11 = acc[mt][nt][3] + b1;
            if (ACT == 1) {
                v00 = 1.0f / (1.0f + expf(-v00));
                v01 = 1.0f / (1.0f + expf(-v01));
                v10 = 1.0f / (1.0f + expf(-v10));
                v11 = 1.0f / (1.0f + expf(-v11));
            } else if (ACT == 2) {
                v00 = 0.5f * v00 * (1.0f + erff(v00 * 0.70710678118654752f));
                v01 = 0.5f * v01 * (1.0f + erff(v01 * 0.70710678118654752f));
                v10 = 0.5f * v10 * (1.0f + erff(v10 * 0.70710678118654752f));
                v11 = 0.5f * v11 * (1.0f + erff(v11 * 0.70710678118654752f));
            }
            *(float2*)(C + (size_t)m       * N + n) = make_float2(v00, v01);
            *(float2*)(C + (size_t)(m + 8) * N + n) = make_float2(v10, v11);
        }
    }
}

// ---------------- attention ----------------
__global__ __launch_bounds__(128) void attn_kernel(
    const float* __restrict__ Q, const float* __restrict__ K,
    const float* __restrict__ V, float* __restrict__ O)
{
    int row = blockIdx.x;
    int b = row / SEQ, i = row % SEQ;
    int tid = threadIdx.x, warp = tid >> 5, lane = tid & 31;

    __shared__ float sQ[DIM];
    __shared__ float sp[SEQ];

    const float* q = Q + (size_t)row * DIM;
    for (int d = tid; d < DIM; d += 128) sQ[d] = q[d];
    __syncthreads();

    for (int j = warp; j < SEQ; j += 4) {
        float s = 0.f;
        if (j <= i) {
            const float* kp = K + ((size_t)b * SEQ + j) * DIM;
            for (int d = lane; d < DIM; d += 32)
                s += fminf(1.0f - sQ[d] + kp[d], 1.0f);
            #pragma unroll
            for (int o = 16; o; o >>= 1) s += __shfl_xor_sync(0xffffffffu, s, o);
            s *= (10.0f / (float)DIM);
        }
        if (lane == 0) sp[j] = s;
    }
    __syncthreads();

    if (warp == 0) {
        float m = -1e30f;
        for (int j = lane; j < SEQ; j += 32) m = fmaxf(m, sp[j]);
        #pragma unroll
        for (int o = 16; o; o >>= 1) m = fmaxf(m, __shfl_xor_sync(0xffffffffu, m, o));
        float sum = 0.f;
        float e0 = 0.f, e1 = 0.f;
        if (lane      < SEQ) { e0 = expf(sp[lane]      - m); sum += e0; }
        if (lane + 32 < SEQ) { e1 = expf(sp[lane + 32] - m); sum += e1; }
        #pragma unroll
        for (int o = 16; o; o >>= 1) sum += __shfl_xor_sync(0xffffffffu, sum, o);
        float inv = 1.0f / sum;
        if (lane      < SEQ) sp[lane]      = e0 * inv;
        if (lane + 32 < SEQ) sp[lane + 32] = e1 * inv;
    }
    __syncthreads();

    float acc[4] = {0.f, 0.f, 0.f, 0.f};
    for (int j = 0; j < SEQ; j++) {
        float p = sp[j];
        const float* v = V + ((size_t)b * SEQ + j) * DIM;
        #pragma unroll
        for (int u = 0; u < 4; u++) acc[u] += p * v[tid + u*128];
    }
    float* o = O + (size_t)row * DIM;
    #pragma unroll
    for (int u = 0; u < 4; u++) o[tid + u*128] = acc[u];
}

// ---------------- fused residual add + LayerNorm ----------------
__global__ __launch_bounds__(128) void add_ln_kernel(
    const float* __restrict__ a, const float* __restrict__ r,
    const float* __restrict__ g, const float* __restrict__ be,
    float* __restrict__ out)
{
    int row = blockIdx.x, tid = threadIdx.x;
    const float* pa = a + (size_t)row * DIM;
    const float* pr = r + (size_t)row * DIM;

    float v[4];
    float sum = 0.f;
    #pragma unroll
    for (int u = 0; u < 4; u++) {
        int d = tid + u*128;
        v[u] = pa[d] + pr[d];
        sum += v[u];
    }
    __shared__ float red[4];
    #pragma unroll
    for (int o = 16; o; o >>= 1) sum += __shfl_xor_sync(0xffffffffu, sum, o);
    if ((tid & 31) == 0) red[tid >> 5] = sum;
    __syncthreads();
    float mean = (red[0] + red[1] + red[2] + red[3]) * (1.0f / DIM);

    float vs = 0.f;
    #pragma unroll
    for (int u = 0; u < 4; u++) { float d = v[u] - mean; vs += d * d; }
    #pragma unroll
    for (int o = 16; o; o >>= 1) vs += __shfl_xor_sync(0xffffffffu, vs, o);
    __shared__ float red2[4];
    if ((tid & 31) == 0) red2[tid >> 5] = vs;
    __syncthreads();
    float var = (red2[0] + red2[1] + red2[2] + red2[3]) * (1.0f / DIM);
    float inv = rsqrtf(var + LN_EPS);

    float* po = out + (size_t)row * DIM;
    #pragma unroll
    for (int u = 0; u < 4; u++) {
        int d = tid + u*128;
        po[d] = (v[u] - mean) * inv * g[d] + be[d];
    }
}

// ---------------- launch ----------------
extern "C" void kernel_launch(void* const* d_in, const int* in_sizes, int n_in,
                              void* d_out, int out_size)
{
    const int*   idx = (const int*)  d_in[0];
    const float* emb = (const float*)d_in[1];
    const float* pos = (const float*)d_in[2];
    const float* wq  = (const float*)d_in[3];
    const float* bq  = (const float*)d_in[4];
    const float* wk  = (const float*)d_in[5];
    const float* bk  = (const float*)d_in[6];
    const float* wv  = (const float*)d_in[7];
    const float* bv  = (const float*)d_in[8];
    const float* w1  = (const float*)d_in[9];
    const float* b1  = (const float*)d_in[10];
    const float* w2  = (const float*)d_in[11];
    const float* b2  = (const float*)d_in[12];
    const float* g1  = (const float*)d_in[13];
    const float* be1 = (const float*)d_in[14];
    const float* g2  = (const float*)d_in[15];
    const float* be2 = (const float*)d_in[16];
    const float* wo  = (const float*)d_in[17];
    const float* bo  = (const float*)d_in[18];
    float* out = (float*)d_out;

    float *x0, *Qb, *Kb, *Vb, *att, *x1, *h, *f, *x2;
    cudaGetSymbolAddress((void**)&x0,  g_x0);
    cudaGetSymbolAddress((void**)&Qb,  g_Q);
    cudaGetSymbolAddress((void**)&Kb,  g_K);
    cudaGetSymbolAddress((void**)&Vb,  g_V);
    cudaGetSymbolAddress((void**)&att, g_att);
    cudaGetSymbolAddress((void**)&x1,  g_x1);
    cudaGetSymbolAddress((void**)&h,   g_h);
    cudaGetSymbolAddress((void**)&f,   g_f);
    cudaGetSymbolAddress((void**)&x2,  g_x2);

    cudaFuncSetAttribute(gemm_tf32_pipe<0>, cudaFuncAttributeMaxDynamicSharedMemorySize, SMEM_BYTES);
    cudaFuncSetAttribute(gemm_tf32_pipe<1>, cudaFuncAttributeMaxDynamicSharedMemorySize, SMEM_BYTES);
    cudaFuncSetAttribute(gemm_tf32_pipe<2>, cudaFuncAttributeMaxDynamicSharedMemorySize, SMEM_BYTES);

    // 1. embed
    embed_kernel<<<ROWS, 128>>>(idx, emb, pos, x0);

    // 2. Q,K,V projections (tf32; sigmoid fused for Q,K).  N=512 -> bn grid 2
    dim3 blk(256);
    dim3 g_d(DIM/256, ROWS/128);       // (2, 50)
    gemm_tf32_pipe<1><<<g_d, blk, SMEM_BYTES>>>(x0, wq, bq, Qb, ROWS, DIM, DIM);
    gemm_tf32_pipe<1><<<g_d, blk, SMEM_BYTES>>>(x0, wk, bk, Kb, ROWS, DIM, DIM);
    gemm_tf32_pipe<0><<<g_d, blk, SMEM_BYTES>>>(x0, wv, bv, Vb, ROWS, DIM, DIM);

    // 3. Lukasiewicz attention
    attn_kernel<<<ROWS, 128>>>(Qb, Kb, Vb, att);

    // 4. LN1(x0 + att)
    add_ln_kernel<<<ROWS, 128>>>(x0, att, g1, be1, x1);

    // 5. FFN (tf32, gelu fused)
    dim3 g_h1(HID/256, ROWS/128);      // (8, 50)
    gemm_tf32_pipe<2><<<g_h1, blk, SMEM_BYTES>>>(x1, w1, b1, h, ROWS, HID, DIM);
    gemm_tf32_pipe<0><<<g_d,  blk, SMEM_BYTES>>>(h,  w2, b2, f, ROWS, DIM, HID);

    // 6. LN2(x1 + f)
    add_ln_kernel<<<ROWS, 128>>>(x1, f, g2, be2, x2);

    // 7. output projection -> d_out (tf32)
    dim3 g_o(VOCAB/256, ROWS/128);     // (125, 50)
    gemm_tf32_pipe<0><<<g_o, blk, SMEM_BYTES>>>(x2, wo, bo, out, ROWS, VOCAB, DIM);
}